// round 14
// baseline (speedup 1.0000x reference)
#include <cuda_runtime.h>

#define NV 8192          // variable nodes
#define RC 4096          // check nodes
#define DCD 6            // check degree
#define STR 7            // slots per check (stride 7 -> conflict-free contiguous LDS)
#define EE (NV*3)        // 24576 edges
#define BB 1024          // batch
#define NITER 10
#define TPB 1024         // 32 warps: 16 check-role + 16 var-role
#define HALF 512         // threads per role
#define NCTA (BB/2)      // 512 CTAs, 2 columns each

// All messages live in LOG2 units (x' = x/ln2): ex2/lg2 need no scale muls.
#define L2E2   2.885390082f    // 2/ln2  (llr' = L2E2 * rec)
#define LN2    0.69314718f
#define CLP2   10.96506f       // 2*atanh(0.999)/ln2

// Small global tables only (messages never touch global memory)
__device__ int      d_cedge[RC*DCD];
__device__ int      d_cnt[RC];        // zero-init; re-zeroed by k_sort each run
__device__ unsigned d_slotO[NV*4];    // var v -> {byteoff0, byteoff1, byteoff2, pad}

static __device__ __forceinline__ float fex2(float x){ float y; asm("ex2.approx.f32 %0,%1;":"=f"(y):"f"(x)); return y; }
static __device__ __forceinline__ float flg2(float x){ float y; asm("lg2.approx.f32 %0,%1;":"=f"(y):"f"(x)); return y; }

__global__ void k_build(const int* __restrict__ ec){
    int e = blockIdx.x*blockDim.x + threadIdx.x;
    if(e < EE){
        int c = ec[e];
        int s = atomicAdd(&d_cnt[c], 1);
        d_cedge[c*DCD + s] = e;
    }
}

// Sort each check's 6 edge ids (deterministic regardless of atomic order),
// emit byte-offset var->slot table, re-zero d_cnt for the next run.
__global__ void k_sort(){
    int c = blockIdx.x*blockDim.x + threadIdx.x;
    if(c >= RC) return;
    int v[DCD];
#pragma unroll
    for(int j=0;j<DCD;j++) v[j] = d_cedge[c*DCD+j];
#pragma unroll
    for(int i=0;i<DCD-1;i++)
#pragma unroll
        for(int j=0;j<DCD-1-i;j++)
            if(v[j] > v[j+1]){ int t=v[j]; v[j]=v[j+1]; v[j+1]=t; }
#pragma unroll
    for(int j=0;j<DCD;j++){
        int e = v[j];
        int var = e/3, k = e - 3*var;
        d_slotO[var*4 + k] = (unsigned)((c*STR + j)*4);   // byte offset
    }
    d_cnt[c] = 0;
}

static __device__ __forceinline__ float  smld(const float* m, unsigned o){
    return *(const float*)((const char*)m + o);
}
static __device__ __forceinline__ void smst(float* m, unsigned o, float v){
    *(float*)((char*)m + o) = v;
}

// ---- role helpers (NT = threads cooperating, t in [0,NT)) -----------------

// Check-node update for ALL RC checks (log2-domain messages).
// u = 2^{-|x'|};  a_k = sign(x)*(1-u), b_k = 1+u  (a/b = tanh(x/2));
// c2v'_j = clamp( lg2(B_j+A_j) - lg2(B_j-A_j), +-CLP2 )  via prefix/suffix.
template<int NT>
static __device__ __forceinline__ void check_sub(float* msg, int t){
#pragma unroll
    for(int cc = 0; cc < RC/NT; ++cc){
        int base = (cc*NT + t)*STR;
        float a[DCD], bb[DCD];
#pragma unroll
        for(int j=0;j<DCD;j++){
            float x = msg[base+j];
            float u = fex2(-fabsf(x));            // MUFU.EX2 with -|.| modifier
            a[j]  = copysignf(1.0f - u, x);
            bb[j] = 1.0f + u;
        }
        float pa[DCD], pb[DCD];
        pa[0]=1.0f; pb[0]=1.0f;
#pragma unroll
        for(int j=1;j<DCD;j++){ pa[j]=pa[j-1]*a[j-1]; pb[j]=pb[j-1]*bb[j-1]; }
        float sa=1.0f, sb=1.0f;
#pragma unroll
        for(int j=DCD-1;j>=0;j--){
            float A  = pa[j]*sa;
            float Bp = pb[j]*sb;
            sa *= a[j]; sb *= bb[j];
            float mag = flg2(Bp + A) - flg2(Bp - A);
            msg[base+j] = fminf(fmaxf(mag, -CLP2), CLP2);
        }
    }
}

// Var-node update for ALL NV vars.
template<int NT>
static __device__ __forceinline__ void var_sub(float* msg, const float* __restrict__ rrow,
                                               const uint4* __restrict__ slo, int t){
#pragma unroll
    for(int vv = 0; vv < NV/NT; ++vv){
        int v = vv*NT + t;
        uint4 s = __ldg(&slo[v]);
        float c0 = smld(msg, s.x), c1 = smld(msg, s.y), c2 = smld(msg, s.z);
        float tot = L2E2*__ldg(rrow+v) + c0 + c1 + c2;
        smst(msg, s.x, tot - c0);
        smst(msg, s.y, tot - c1);
        smst(msg, s.z, tot - c2);
    }
}

// Init v2c for ALL NV vars.
template<int NT>
static __device__ __forceinline__ void init_sub(float* msg, const float* __restrict__ rrow,
                                                const uint4* __restrict__ slo, int t){
#pragma unroll
    for(int vv = 0; vv < NV/NT; ++vv){
        int v = vv*NT + t;
        uint4 s = __ldg(&slo[v]);
        float lv = L2E2 * __ldg(rrow+v);
        smst(msg, s.x, lv);
        smst(msg, s.y, lv);
        smst(msg, s.z, lv);
    }
}

// Final posterior + bits for ALL NV vars (convert back: f = ln2*llr' etc.).
template<int NT>
static __device__ __forceinline__ void final_sub(const float* msg, const float* __restrict__ rrow,
                                                 float* __restrict__ orow, float* __restrict__ brow,
                                                 const uint4* __restrict__ slo, int t, int do_bits){
#pragma unroll
    for(int vv = 0; vv < NV/NT; ++vv){
        int v = vv*NT + t;
        uint4 s = __ldg(&slo[v]);
        float sum = smld(msg, s.x) + smld(msg, s.y) + smld(msg, s.z);
        float f = 2.0f*__ldg(rrow+v) + LN2*sum;
        orow[v] = f;
        if(do_bits) brow[v] = (f < 0.0f) ? 1.0f : 0.0f;
    }
}

// ---- warp-specialized pair kernel -----------------------------------------
// 2 columns per CTA (msgA, msgB, 224KB). Warps 0-15 = check role, 16-31 = var
// role. Every stage runs a check phase (MUFU pipe) and a var phase (smem
// crossbar) CONCURRENTLY on different warps -> pipes overlap instead of adding.
__global__ void __launch_bounds__(TPB, 1) k_decode(const float* __restrict__ rec,
                                                   float* __restrict__ out,
                                                   int do_bits){
    extern __shared__ float sm[];
    float* msgA = sm;
    float* msgB = sm + RC*STR;

    const int tid = threadIdx.x;
    const int ca = 2*blockIdx.x, cb = ca + 1;
    const float* __restrict__ rA = rec + (size_t)ca*NV;
    const float* __restrict__ rB = rec + (size_t)cb*NV;
    const uint4* __restrict__ slo = (const uint4*)d_slotO;

    const bool chkrole = (tid < HALF);                       // warps 0-15
    const int t = chkrole ? tid : (tid - HALF);              // 0..511 within role

    // stage 1: init A (all 1024 threads)
    init_sub<TPB>(msgA, rA, slo, tid);
    __syncthreads();

    // stage 2: check A(it1) || init B
    if(chkrole) check_sub<HALF>(msgA, t); else init_sub<HALF>(msgB, rB, slo, t);
    __syncthreads();

    // stages 3..20: { check B(it) || var A(it) ; check A(it+1) || var B(it) }
#pragma unroll 1
    for(int it = 1; it <= NITER-1; ++it){
        if(chkrole) check_sub<HALF>(msgB, t); else var_sub<HALF>(msgA, rA, slo, t);
        __syncthreads();
        if(chkrole) check_sub<HALF>(msgA, t); else var_sub<HALF>(msgB, rB, slo, t);
        __syncthreads();
    }
    // A: check10 done.  B: var9 done.
    // stage 21: check B(it10) || final A
    if(chkrole) check_sub<HALF>(msgB, t);
    else final_sub<HALF>(msgA, rA, out + (size_t)ca*NV, out + (size_t)(BB+ca)*NV, slo, t, do_bits);
    __syncthreads();
    // stage 22: final B (all 1024 threads)
    final_sub<TPB>(msgB, rB, out + (size_t)cb*NV, out + (size_t)(BB+cb)*NV, slo, tid, do_bits);
}

extern "C" void kernel_launch(void* const* d_in, const int* in_sizes, int n_in,
                              void* d_out, int out_size){
    const float* rec = (const float*)d_in[0];
    const int*   ec  = (const int*)d_in[2];   // edge_check (edge_var is repeat(arange(N),3))

    static const int SMEM = 2*RC*STR*4;        // 229376 B (two message arrays)
    cudaFuncSetAttribute(k_decode, cudaFuncAttributeMaxDynamicSharedMemorySize, SMEM);

    k_build<<<EE/256, 256>>>(ec);
    k_sort<<<RC/256, 256>>>();

    int do_bits = (out_size >= 2*NV*BB);
    k_decode<<<NCTA, TPB, SMEM>>>(rec, (float*)d_out, do_bits);
}

// round 15
// speedup vs baseline: 1.8907x; 1.8907x over previous
#include <cuda_runtime.h>

#define NV 8192          // variable nodes
#define RC 4096          // check nodes
#define DCD 6            // check degree
#define STR 7            // slots per check (stride 7 -> conflict-free contiguous LDS)
#define EE (NV*3)        // 24576 edges
#define BB 1024          // batch
#define NITER 10
#define TPB 1024         // 32 warps: 16 check-role + 16 var-role
#define HALF 512         // threads per role
#define NCTA (BB/2)      // 512 CTAs, 2 columns each

// All messages live in LOG2 units (x' = x/ln2): ex2/lg2 need no scale muls.
#define L2E2   2.885390082f    // 2/ln2  (llr' = L2E2 * rec)
#define LN2    0.69314718f
#define CLP2   10.96506f       // 2*atanh(0.999)/ln2

// Small global tables only (messages never touch global memory)
__device__ int            d_cedge[RC*DCD];
__device__ int            d_cnt[RC];        // zero-init; re-zeroed by k_sort each run
__device__ unsigned short d_slotT[NV*4];    // var v -> {slot0, slot1, slot2, pad}

static __device__ __forceinline__ float fex2(float x){ float y; asm("ex2.approx.f32 %0,%1;":"=f"(y):"f"(x)); return y; }
static __device__ __forceinline__ float flg2(float x){ float y; asm("lg2.approx.f32 %0,%1;":"=f"(y):"f"(x)); return y; }

__global__ void k_build(const int* __restrict__ ec){
    int e = blockIdx.x*blockDim.x + threadIdx.x;
    if(e < EE){
        int c = ec[e];
        int s = atomicAdd(&d_cnt[c], 1);
        d_cedge[c*DCD + s] = e;
    }
}

// Sort each check's 6 edge ids (deterministic regardless of atomic order),
// emit packed var->slot table, re-zero d_cnt for the next run.
__global__ void k_sort(){
    int c = blockIdx.x*blockDim.x + threadIdx.x;
    if(c >= RC) return;
    int v[DCD];
#pragma unroll
    for(int j=0;j<DCD;j++) v[j] = d_cedge[c*DCD+j];
#pragma unroll
    for(int i=0;i<DCD-1;i++)
#pragma unroll
        for(int j=0;j<DCD-1-i;j++)
            if(v[j] > v[j+1]){ int t=v[j]; v[j]=v[j+1]; v[j+1]=t; }
#pragma unroll
    for(int j=0;j<DCD;j++){
        int e = v[j];
        int var = e/3, k = e - 3*var;
        d_slotT[var*4 + k] = (unsigned short)(c*STR + j);
    }
    d_cnt[c] = 0;
}

// ---- role helpers (NT = threads cooperating, t in [0,NT)) -----------------

// Check-node update for ALL RC checks (log2-domain messages).
// u = 2^{-|x'|};  a_k = sign(x)*(1-u), b_k = 1+u  (a/b = tanh(x/2));
// c2v'_j = clamp( lg2(B_j+A_j) - lg2(B_j-A_j), +-CLP2 )  via prefix/suffix.
template<int NT>
static __device__ __forceinline__ void check_sub(float* msg, int t){
#pragma unroll
    for(int cc = 0; cc < RC/NT; ++cc){
        int base = (cc*NT + t)*STR;
        float a[DCD], bb[DCD];
#pragma unroll
        for(int j=0;j<DCD;j++){
            float x = msg[base+j];
            float u = fex2(-fabsf(x));            // MUFU.EX2 with -|.| modifiers
            a[j]  = copysignf(1.0f - u, x);
            bb[j] = 1.0f + u;
        }
        float pa[DCD], pb[DCD];
        pa[0]=1.0f; pb[0]=1.0f;
#pragma unroll
        for(int j=1;j<DCD;j++){ pa[j]=pa[j-1]*a[j-1]; pb[j]=pb[j-1]*bb[j-1]; }
        float sa=1.0f, sb=1.0f;
#pragma unroll
        for(int j=DCD-1;j>=0;j--){
            float A  = pa[j]*sa;
            float Bp = pb[j]*sb;
            sa *= a[j]; sb *= bb[j];
            float mag = flg2(Bp + A) - flg2(Bp - A);
            msg[base+j] = fminf(fmaxf(mag, -CLP2), CLP2);
        }
    }
}

// Var-node update for ALL NV vars.
template<int NT>
static __device__ __forceinline__ void var_sub(float* msg, const float* __restrict__ rrow,
                                               const uint2* __restrict__ slt, int t){
#pragma unroll
    for(int vv = 0; vv < NV/NT; ++vv){
        int v = vv*NT + t;
        uint2 s = slt[v];
        int s0 = s.x & 0xFFFF, s1 = s.x >> 16, s2 = s.y & 0xFFFF;
        float c0 = msg[s0], c1 = msg[s1], c2 = msg[s2];
        float tot = L2E2*__ldg(rrow+v) + c0 + c1 + c2;
        msg[s0] = tot - c0;
        msg[s1] = tot - c1;
        msg[s2] = tot - c2;
    }
}

// Init v2c for ALL NV vars.
template<int NT>
static __device__ __forceinline__ void init_sub(float* msg, const float* __restrict__ rrow,
                                                const uint2* __restrict__ slt, int t){
#pragma unroll
    for(int vv = 0; vv < NV/NT; ++vv){
        int v = vv*NT + t;
        uint2 s = slt[v];
        float lv = L2E2 * __ldg(rrow+v);
        msg[s.x & 0xFFFF] = lv;
        msg[s.x >> 16]    = lv;
        msg[s.y & 0xFFFF] = lv;
    }
}

// Final posterior + bits for ALL NV vars (convert back: f = 2*rec + ln2*sum).
template<int NT>
static __device__ __forceinline__ void final_sub(const float* msg, const float* __restrict__ rrow,
                                                 float* __restrict__ orow, float* __restrict__ brow,
                                                 const uint2* __restrict__ slt, int t, int do_bits){
#pragma unroll
    for(int vv = 0; vv < NV/NT; ++vv){
        int v = vv*NT + t;
        uint2 s = slt[v];
        float sum = msg[s.x & 0xFFFF] + msg[s.x >> 16] + msg[s.y & 0xFFFF];
        float f = 2.0f*__ldg(rrow+v) + LN2*sum;
        orow[v] = f;
        if(do_bits) brow[v] = (f < 0.0f) ? 1.0f : 0.0f;
    }
}

// ---- warp-specialized pair kernel -----------------------------------------
// 2 columns per CTA (msgA, msgB, 224KB). Warps 0-15 = check role, 16-31 = var
// role. Every stage runs a check phase (MUFU pipe) and a var phase (smem
// crossbar) CONCURRENTLY on different warps -> pipes overlap instead of adding.
__global__ void __launch_bounds__(TPB, 1) k_decode(const float* __restrict__ rec,
                                                   float* __restrict__ out,
                                                   int do_bits){
    extern __shared__ float sm[];
    float* msgA = sm;
    float* msgB = sm + RC*STR;

    const int tid = threadIdx.x;
    const int ca = 2*blockIdx.x, cb = ca + 1;
    const float* __restrict__ rA = rec + (size_t)ca*NV;
    const float* __restrict__ rB = rec + (size_t)cb*NV;
    const uint2* __restrict__ slt = (const uint2*)d_slotT;   // {s0|s1, s2|pad}

    const bool chkrole = (tid < HALF);                       // warps 0-15
    const int t = chkrole ? tid : (tid - HALF);              // 0..511 within role

    // stage 1: init A (all 1024 threads)
    init_sub<TPB>(msgA, rA, slt, tid);
    __syncthreads();

    // stage 2: check A(it1) || init B
    if(chkrole) check_sub<HALF>(msgA, t); else init_sub<HALF>(msgB, rB, slt, t);
    __syncthreads();

    // stages 3..20: { check B(it) || var A(it) ; check A(it+1) || var B(it) }
#pragma unroll 1
    for(int it = 1; it <= NITER-1; ++it){
        if(chkrole) check_sub<HALF>(msgB, t); else var_sub<HALF>(msgA, rA, slt, t);
        __syncthreads();
        if(chkrole) check_sub<HALF>(msgA, t); else var_sub<HALF>(msgB, rB, slt, t);
        __syncthreads();
    }
    // A: check10 done.  B: var9 done.
    // stage 21: check B(it10) || final A
    if(chkrole) check_sub<HALF>(msgB, t);
    else final_sub<HALF>(msgA, rA, out + (size_t)ca*NV, out + (size_t)(BB+ca)*NV, slt, t, do_bits);
    __syncthreads();
    // stage 22: final B (all 1024 threads)
    final_sub<TPB>(msgB, rB, out + (size_t)cb*NV, out + (size_t)(BB+cb)*NV, slt, tid, do_bits);
}

extern "C" void kernel_launch(void* const* d_in, const int* in_sizes, int n_in,
                              void* d_out, int out_size){
    const float* rec = (const float*)d_in[0];
    const int*   ec  = (const int*)d_in[2];   // edge_check (edge_var is repeat(arange(N),3))

    static const int SMEM = 2*RC*STR*4;        // 229376 B (two message arrays)
    cudaFuncSetAttribute(k_decode, cudaFuncAttributeMaxDynamicSharedMemorySize, SMEM);

    k_build<<<EE/256, 256>>>(ec);
    k_sort<<<RC/256, 256>>>();

    int do_bits = (out_size >= 2*NV*BB);
    k_decode<<<NCTA, TPB, SMEM>>>(rec, (float*)d_out, do_bits);
}

// round 16
// speedup vs baseline: 1.8965x; 1.0031x over previous
#include <cuda_runtime.h>

#define NV 8192          // variable nodes
#define RC 4096          // check nodes
#define DCD 6            // check degree
#define STR 7            // slots per check (stride 7 -> conflict-free contiguous LDS)
#define EE (NV*3)        // 24576 edges
#define BB 1024          // batch
#define NITER 10
#define TPB 1024         // 32 warps: 16 check-role + 16 var-role
#define HALF 512         // threads per role
#define NCTA (BB/2)      // 512 CTAs, 2 columns each

// All messages live in LOG2 units (x' = x/ln2): ex2/lg2 need no scale muls.
#define L2E2   2.885390082f    // 2/ln2  (llr' = L2E2 * rec)
#define LN2    0.69314718f
#define CLP2   10.96506f       // 2*atanh(0.999)/ln2

// Small global tables only (messages never touch global memory)
__device__ int            d_cedge[RC*DCD];
__device__ int            d_cnt[RC];        // zero-init; re-zeroed by k_sort each run
__device__ unsigned short d_slotT[NV*4];    // var v -> {slotR0, slotR1, slotR2, pad}

static __device__ __forceinline__ float fex2(float x){ float y; asm("ex2.approx.f32 %0,%1;":"=f"(y):"f"(x)); return y; }
static __device__ __forceinline__ float flg2(float x){ float y; asm("lg2.approx.f32 %0,%1;":"=f"(y):"f"(x)); return y; }

__global__ void k_build(const int* __restrict__ ec){
    int e = blockIdx.x*blockDim.x + threadIdx.x;
    if(e < EE){
        int c = ec[e];
        int s = atomicAdd(&d_cnt[c], 1);
        d_cedge[c*DCD + s] = e;
    }
}

// Sort each check's 6 edge ids (deterministic regardless of atomic order),
// emit packed var->slot table, re-zero d_cnt for the next run.
__global__ void k_sort(){
    int c = blockIdx.x*blockDim.x + threadIdx.x;
    if(c >= RC) return;
    int v[DCD];
#pragma unroll
    for(int j=0;j<DCD;j++) v[j] = d_cedge[c*DCD+j];
#pragma unroll
    for(int i=0;i<DCD-1;i++)
#pragma unroll
        for(int j=0;j<DCD-1-i;j++)
            if(v[j] > v[j+1]){ int t=v[j]; v[j]=v[j+1]; v[j+1]=t; }
#pragma unroll
    for(int j=0;j<DCD;j++){
        int e = v[j];
        int var = e/3, k = e - 3*var;
        d_slotT[var*4 + k] = (unsigned short)(c*STR + j);
    }
    d_cnt[c] = 0;
}

// Bank-schedule the var phase: for each 32-var lane-group, greedily permute
// each var's 3 slots across the 3 access rounds to minimize smem bank
// collisions within the warp. Identical greedy decisions to the slow array
// version, but counters live in registers as nibble-packed uint64s (no LDL).
__global__ void k_sched(){
    int g = blockIdx.x*blockDim.x + threadIdx.x;   // group of 32 consecutive vars
    if(g >= NV/32) return;
    unsigned long long lo[3] = {0,0,0}, hi[3] = {0,0,0};   // nibble counts, banks 0-15 / 16-31
    const unsigned char perms[6][3] = {{0,1,2},{0,2,1},{1,0,2},{1,2,0},{2,0,1},{2,1,0}};
    for(int l=0;l<32;l++){
        int v = g*32 + l;
        unsigned short s[3] = {d_slotT[v*4], d_slotT[v*4+1], d_slotT[v*4+2]};
        int best = 0, bestcost = 1<<30;
#pragma unroll
        for(int p=0;p<6;p++){
            int cost = 0;
#pragma unroll
            for(int r=0;r<3;r++){
                int b = s[perms[p][r]] & 31;
                unsigned long long w = (b < 16) ? lo[r] : hi[r];
                cost += (int)((w >> ((b & 15)*4)) & 0xFULL);
            }
            if(cost < bestcost){ bestcost = cost; best = p; }
        }
        unsigned short t[3] = {s[perms[best][0]], s[perms[best][1]], s[perms[best][2]]};
#pragma unroll
        for(int r=0;r<3;r++){
            int b = t[r] & 31;
            unsigned long long inc = 1ULL << ((b & 15)*4);
            if(b < 16) lo[r] += inc; else hi[r] += inc;
        }
        d_slotT[v*4]   = t[0];
        d_slotT[v*4+1] = t[1];
        d_slotT[v*4+2] = t[2];
    }
}

// ---- role helpers (NT = threads cooperating, t in [0,NT)) -----------------

// Check-node update for ALL RC checks (log2-domain messages).
// u = 2^{-|x'|};  a_k = sign(x)*(1-u), b_k = 1+u  (a/b = tanh(x/2));
// c2v'_j = clamp( lg2(B_j+A_j) - lg2(B_j-A_j), +-CLP2 )  via prefix/suffix.
template<int NT>
static __device__ __forceinline__ void check_sub(float* msg, int t){
#pragma unroll
    for(int cc = 0; cc < RC/NT; ++cc){
        int base = (cc*NT + t)*STR;
        float a[DCD], bb[DCD];
#pragma unroll
        for(int j=0;j<DCD;j++){
            float x = msg[base+j];
            float u = fex2(-fabsf(x));            // MUFU.EX2 with -|.| modifiers
            a[j]  = copysignf(1.0f - u, x);
            bb[j] = 1.0f + u;
        }
        float pa[DCD], pb[DCD];
        pa[0]=1.0f; pb[0]=1.0f;
#pragma unroll
        for(int j=1;j<DCD;j++){ pa[j]=pa[j-1]*a[j-1]; pb[j]=pb[j-1]*bb[j-1]; }
        float sa=1.0f, sb=1.0f;
#pragma unroll
        for(int j=DCD-1;j>=0;j--){
            float A  = pa[j]*sa;
            float Bp = pb[j]*sb;
            sa *= a[j]; sb *= bb[j];
            float mag = flg2(Bp + A) - flg2(Bp - A);
            msg[base+j] = fminf(fmaxf(mag, -CLP2), CLP2);
        }
    }
}

// Var-node update for ALL NV vars (3 bank-scheduled access rounds).
template<int NT>
static __device__ __forceinline__ void var_sub(float* msg, const float* __restrict__ rrow,
                                               const uint2* __restrict__ slt, int t){
#pragma unroll
    for(int vv = 0; vv < NV/NT; ++vv){
        int v = vv*NT + t;
        uint2 s = slt[v];
        int s0 = s.x & 0xFFFF, s1 = s.x >> 16, s2 = s.y & 0xFFFF;
        float c0 = msg[s0], c1 = msg[s1], c2 = msg[s2];
        float tot = L2E2*__ldg(rrow+v) + c0 + c1 + c2;
        msg[s0] = tot - c0;
        msg[s1] = tot - c1;
        msg[s2] = tot - c2;
    }
}

// Init v2c for ALL NV vars.
template<int NT>
static __device__ __forceinline__ void init_sub(float* msg, const float* __restrict__ rrow,
                                                const uint2* __restrict__ slt, int t){
#pragma unroll
    for(int vv = 0; vv < NV/NT; ++vv){
        int v = vv*NT + t;
        uint2 s = slt[v];
        float lv = L2E2 * __ldg(rrow+v);
        msg[s.x & 0xFFFF] = lv;
        msg[s.x >> 16]    = lv;
        msg[s.y & 0xFFFF] = lv;
    }
}

// Final posterior + bits for ALL NV vars (convert back: f = 2*rec + ln2*sum).
template<int NT>
static __device__ __forceinline__ void final_sub(const float* msg, const float* __restrict__ rrow,
                                                 float* __restrict__ orow, float* __restrict__ brow,
                                                 const uint2* __restrict__ slt, int t, int do_bits){
#pragma unroll
    for(int vv = 0; vv < NV/NT; ++vv){
        int v = vv*NT + t;
        uint2 s = slt[v];
        float sum = msg[s.x & 0xFFFF] + msg[s.x >> 16] + msg[s.y & 0xFFFF];
        float f = 2.0f*__ldg(rrow+v) + LN2*sum;
        orow[v] = f;
        if(do_bits) brow[v] = (f < 0.0f) ? 1.0f : 0.0f;
    }
}

// ---- warp-specialized pair kernel -----------------------------------------
// 2 columns per CTA (msgA, msgB, 224KB). Warps 0-15 = check role, 16-31 = var
// role. Every stage runs a check phase (MUFU pipe) and a var phase (smem
// crossbar) CONCURRENTLY on different warps -> pipes overlap instead of adding.
__global__ void __launch_bounds__(TPB, 1) k_decode(const float* __restrict__ rec,
                                                   float* __restrict__ out,
                                                   int do_bits){
    extern __shared__ float sm[];
    float* msgA = sm;
    float* msgB = sm + RC*STR;

    const int tid = threadIdx.x;
    const int ca = 2*blockIdx.x, cb = ca + 1;
    const float* __restrict__ rA = rec + (size_t)ca*NV;
    const float* __restrict__ rB = rec + (size_t)cb*NV;
    const uint2* __restrict__ slt = (const uint2*)d_slotT;   // {sR0|sR1, sR2|pad}

    const bool chkrole = (tid < HALF);                       // warps 0-15
    const int t = chkrole ? tid : (tid - HALF);              // 0..511 within role

    // stage 1: init A (all 1024 threads)
    init_sub<TPB>(msgA, rA, slt, tid);
    __syncthreads();

    // stage 2: check A(it1) || init B
    if(chkrole) check_sub<HALF>(msgA, t); else init_sub<HALF>(msgB, rB, slt, t);
    __syncthreads();

    // stages 3..20: { check B(it) || var A(it) ; check A(it+1) || var B(it) }
#pragma unroll 1
    for(int it = 1; it <= NITER-1; ++it){
        if(chkrole) check_sub<HALF>(msgB, t); else var_sub<HALF>(msgA, rA, slt, t);
        __syncthreads();
        if(chkrole) check_sub<HALF>(msgA, t); else var_sub<HALF>(msgB, rB, slt, t);
        __syncthreads();
    }
    // A: check10 done.  B: var9 done.
    // stage 21: check B(it10) || final A
    if(chkrole) check_sub<HALF>(msgB, t);
    else final_sub<HALF>(msgA, rA, out + (size_t)ca*NV, out + (size_t)(BB+ca)*NV, slt, t, do_bits);
    __syncthreads();
    // stage 22: final B (all 1024 threads)
    final_sub<TPB>(msgB, rB, out + (size_t)cb*NV, out + (size_t)(BB+cb)*NV, slt, tid, do_bits);
}

extern "C" void kernel_launch(void* const* d_in, const int* in_sizes, int n_in,
                              void* d_out, int out_size){
    const float* rec = (const float*)d_in[0];
    const int*   ec  = (const int*)d_in[2];   // edge_check (edge_var is repeat(arange(N),3))

    static const int SMEM = 2*RC*STR*4;        // 229376 B (two message arrays)
    cudaFuncSetAttribute(k_decode, cudaFuncAttributeMaxDynamicSharedMemorySize, SMEM);

    k_build<<<EE/256, 256>>>(ec);
    k_sort<<<RC/256, 256>>>();
    k_sched<<<1, NV/32>>>();                   // 256 threads, one per 32-var group

    int do_bits = (out_size >= 2*NV*BB);
    k_decode<<<NCTA, TPB, SMEM>>>(rec, (float*)d_out, do_bits);
}